// round 2
// baseline (speedup 1.0000x reference)
#include <cuda_runtime.h>
#include <math.h>

#define B_    4
#define DE    128
#define DO    512
#define THW   10240
#define HW    1024
#define NCHUNK 40          // t-chunks of 256 for softmax partial sums
#define SCALE 0.08838834764831845f   // 1/sqrt(128)
#define INV2SIG2 (1.0f/18.0f)        // 1/(2*3^2)

// ---- device scratch (no allocations allowed) ----
__device__ float  g_p[(size_t)B_ * THW * HW];     // correlation matrix p (168 MB)
__device__ float2 g_center[B_ * THW];             // argmax gaussian centers (cx, cy)
__device__ float  g_part[B_ * NCHUNK * HW];       // partial softmax sums
__device__ float  g_inv[B_ * HW];                 // 1/sum per (b,q)

// ============================================================
// Kernel 1: p[b,t,q] = (1/sqrt(De)) * sum_d mi[b,d,t] * qi[b,d,q]
// A = mi [De][THW] row-major (contiguous in t), Bq = qi [De][HW]
// 128x128x16 tile, 256 threads, 8x8 per thread.
// ============================================================
__global__ void __launch_bounds__(256) gemm_p_kernel(
    const float* __restrict__ mi, const float* __restrict__ qi,
    float* __restrict__ p)
{
    const int b = blockIdx.z;
    const float* A  = mi + (size_t)b * DE * THW;
    const float* Bq = qi + (size_t)b * DE * HW;
    float* C        = p  + (size_t)b * THW * HW;
    const int t0 = blockIdx.y * 128;
    const int q0 = blockIdx.x * 128;

    __shared__ float As[16][128];
    __shared__ float Bs[16][128];

    const int tid = threadIdx.x;
    const int tx = tid & 15;   // 16 cols of threads
    const int ty = tid >> 4;   // 16 rows of threads
    float acc[8][8];
    #pragma unroll
    for (int i = 0; i < 8; i++)
        #pragma unroll
        for (int j = 0; j < 8; j++) acc[i][j] = 0.f;

    for (int k0 = 0; k0 < DE; k0 += 16) {
        #pragma unroll
        for (int i = 0; i < 2; i++) {
            int idx = tid + i * 256;       // 0..511
            int kk = idx >> 5;             // 0..15
            int mm = (idx & 31) << 2;      // 0..124
            *(float4*)&As[kk][mm] =
                *(const float4*)(A + (size_t)(k0 + kk) * THW + t0 + mm);
            *(float4*)&Bs[kk][mm] =
                *(const float4*)(Bq + (size_t)(k0 + kk) * HW + q0 + mm);
        }
        __syncthreads();
        #pragma unroll
        for (int k = 0; k < 16; k++) {
            float ar[8], br[8];
            #pragma unroll
            for (int i = 0; i < 8; i++) ar[i] = As[k][ty * 8 + i];
            #pragma unroll
            for (int j = 0; j < 8; j++) br[j] = Bs[k][tx * 8 + j];
            #pragma unroll
            for (int i = 0; i < 8; i++)
                #pragma unroll
                for (int j = 0; j < 8; j++)
                    acc[i][j] += ar[i] * br[j];
        }
        __syncthreads();
    }
    #pragma unroll
    for (int i = 0; i < 8; i++) {
        size_t row = (size_t)(t0 + ty * 8 + i) * HW + q0 + tx * 8;
        #pragma unroll
        for (int j = 0; j < 8; j += 4) {
            float4 v = make_float4(acc[i][j] * SCALE, acc[i][j+1] * SCALE,
                                   acc[i][j+2] * SCALE, acc[i][j+3] * SCALE);
            *(float4*)(C + row + j) = v;
        }
    }
}

// ============================================================
// Kernel 2: argmax over q (1024 contiguous) per (b,t) row; first-index ties.
// One warp per row.
// ============================================================
__global__ void __launch_bounds__(256) argmax_kernel(const float* __restrict__ p)
{
    int gwarp = (blockIdx.x * 256 + threadIdx.x) >> 5;
    int lane  = threadIdx.x & 31;
    if (gwarp >= B_ * THW) return;
    const float* row = p + (size_t)gwarp * HW;

    float best = -3.4e38f;
    int bi = 0;
    #pragma unroll 4
    for (int i = lane; i < HW; i += 32) {
        float v = row[i];
        if (v > best) { best = v; bi = i; }   // increasing i -> keeps first max
    }
    #pragma unroll
    for (int off = 16; off > 0; off >>= 1) {
        float ov = __shfl_down_sync(0xffffffffu, best, off);
        int   oi = __shfl_down_sync(0xffffffffu, bi,   off);
        if (ov > best || (ov == best && oi < bi)) { best = ov; bi = oi; }
    }
    if (lane == 0)
        g_center[gwarp] = make_float2((float)(bi & 31), (float)(bi >> 5));
}

// ============================================================
// Kernel 3a: e[b,t,q] = exp(p[b,t,q] - d^2(t,q)/(2 sigma^2)); partial sums
// over 256-t chunks. (softmax normalizer cancels against gaussian renorm)
// ============================================================
__global__ void __launch_bounds__(256) exp_partial_kernel(
    const float* __restrict__ p, float* __restrict__ e)
{
    const int b  = blockIdx.z;
    const int q  = blockIdx.x * 256 + threadIdx.x;
    const int t0 = blockIdx.y * 256;
    const float qx = (float)(q & 31);
    const float qy = (float)(q >> 5);

    const float2* cen = g_center + (size_t)b * THW + t0;
    const float*  pc  = p + ((size_t)b * THW + t0) * HW + q;
    float*        ec  = e + ((size_t)b * THW + t0) * HW + q;

    float s = 0.f;
    #pragma unroll 4
    for (int t = 0; t < 256; t++) {
        float2 c = cen[t];
        float dx = qx - c.x, dy = qy - c.y;
        float v = __expf(pc[(size_t)t * HW] - (dx * dx + dy * dy) * INV2SIG2);
        ec[(size_t)t * HW] = v;
        s += v;
    }
    g_part[((size_t)b * NCHUNK + blockIdx.y) * HW + q] = s;
}

// Kernel 3b: reduce partials -> g_inv (deterministic fixed order)
__global__ void __launch_bounds__(256) inv_kernel()
{
    int i = blockIdx.x * 256 + threadIdx.x;   // 0..4095 = b*HW+q
    int b = i >> 10, q = i & 1023;
    float s = 0.f;
    #pragma unroll
    for (int c = 0; c < NCHUNK; c++)
        s += g_part[((size_t)b * NCHUNK + c) * HW + q];
    g_inv[i] = 1.0f / s;
}

// Kernel 3c: p_w = e * inv[b,q]  (in place, vectorized)
__global__ void __launch_bounds__(256) scale_kernel(float* __restrict__ e)
{
    const size_t total4 = (size_t)B_ * THW * HW / 4;
    const size_t stride = (size_t)gridDim.x * 256;
    for (size_t i = blockIdx.x * 256ull + threadIdx.x; i < total4; i += stride) {
        float4 v = ((float4*)e)[i];
        size_t q4 = i & 255;                         // HW/4 = 256 (pow2)
        size_t b  = i / ((size_t)THW * HW / 4);
        float4 inv = ((const float4*)g_inv)[b * 256 + q4];
        v.x *= inv.x; v.y *= inv.y; v.z *= inv.z; v.w *= inv.w;
        ((float4*)e)[i] = v;
    }
}

// ============================================================
// Kernel 4: mem[b,o,q] = sum_t mo[b,o,t] * p_w[b,t,q]
// A = mo [Do][THW] row-major (contiguous in t=k), B = p_w [THW][HW]
// writes directly into out[b, o, :] (first half of channel dim).
// ============================================================
__global__ void __launch_bounds__(256) gemm_mem_kernel(
    const float* __restrict__ mo, const float* __restrict__ pw,
    float* __restrict__ out)
{
    const int b = blockIdx.z;
    const float* A  = mo + (size_t)b * DO * THW;
    const float* Bm = pw + (size_t)b * THW * HW;
    float* C        = out + (size_t)b * 2 * DO * HW;
    const int o0 = blockIdx.y * 128;
    const int q0 = blockIdx.x * 128;

    __shared__ float As[16][128];
    __shared__ float Bs[16][128];

    const int tid = threadIdx.x;
    const int tx = tid & 15;
    const int ty = tid >> 4;
    float acc[8][8];
    #pragma unroll
    for (int i = 0; i < 8; i++)
        #pragma unroll
        for (int j = 0; j < 8; j++) acc[i][j] = 0.f;

    for (int k0 = 0; k0 < THW; k0 += 16) {
        #pragma unroll
        for (int i = 0; i < 2; i++) {
            int idx = tid + i * 256;          // 0..511
            // A: row mm (o), 4 k's -> transpose into As[k][m]
            int mm = idx >> 2;                // 0..127
            int kk = (idx & 3) << 2;          // 0,4,8,12
            float4 a = *(const float4*)(A + (size_t)(o0 + mm) * THW + k0 + kk);
            As[kk + 0][mm] = a.x; As[kk + 1][mm] = a.y;
            As[kk + 2][mm] = a.z; As[kk + 3][mm] = a.w;
            // B: row kb (t), contiguous in q
            int kb = idx >> 5;
            int nb = (idx & 31) << 2;
            *(float4*)&Bs[kb][nb] =
                *(const float4*)(Bm + (size_t)(k0 + kb) * HW + q0 + nb);
        }
        __syncthreads();
        #pragma unroll
        for (int k = 0; k < 16; k++) {
            float ar[8], br[8];
            #pragma unroll
            for (int i = 0; i < 8; i++) ar[i] = As[k][ty * 8 + i];
            #pragma unroll
            for (int j = 0; j < 8; j++) br[j] = Bs[k][tx * 8 + j];
            #pragma unroll
            for (int i = 0; i < 8; i++)
                #pragma unroll
                for (int j = 0; j < 8; j++)
                    acc[i][j] += ar[i] * br[j];
        }
        __syncthreads();
    }
    #pragma unroll
    for (int i = 0; i < 8; i++) {
        size_t row = (size_t)(o0 + ty * 8 + i) * HW + q0 + tx * 8;
        #pragma unroll
        for (int j = 0; j < 8; j += 4) {
            float4 v = make_float4(acc[i][j], acc[i][j+1], acc[i][j+2], acc[i][j+3]);
            *(float4*)(C + row + j) = v;
        }
    }
}

// Kernel 5: copy q_out into second half of channel dim of out
__global__ void __launch_bounds__(256) copy_qout_kernel(
    const float* __restrict__ q_out, float* __restrict__ out)
{
    const size_t per_b4 = (size_t)DO * HW / 4;     // 131072 float4 per batch
    const size_t total4 = (size_t)B_ * per_b4;
    const size_t stride = (size_t)gridDim.x * 256;
    const float4* src = (const float4*)q_out;
    float4* dst = (float4*)out;
    for (size_t i = blockIdx.x * 256ull + threadIdx.x; i < total4; i += stride) {
        size_t b = i / per_b4;
        size_t r = i - b * per_b4;
        dst[b * 2 * per_b4 + per_b4 + r] = src[i];
    }
}

// ============================================================
extern "C" void kernel_launch(void* const* d_in, const int* in_sizes, int n_in,
                              void* d_out, int out_size)
{
    const float* m_in  = (const float*)d_in[0];  // [B,De,T,H,W]
    const float* m_out = (const float*)d_in[1];  // [B,Do,T,H,W]
    const float* q_in  = (const float*)d_in[2];  // [B,De,H,W]
    const float* q_out = (const float*)d_in[3];  // [B,Do,H,W]
    float* out = (float*)d_out;

    float* p = nullptr;
    cudaGetSymbolAddress((void**)&p, g_p);

    // p_w output region: after mem_out (B * 2*Do * H * W floats), if present
    const size_t memout_elems = (size_t)B_ * 2 * DO * HW;          // 4,194,304
    const size_t pw_elems     = (size_t)B_ * THW * HW;             // 41,943,040
    float* e = ((size_t)out_size >= memout_elems + pw_elems)
                   ? (out + memout_elems)
                   : p;   // fallback: keep p_w in scratch (in-place over p)

    // 1) correlation GEMM
    dim3 g1(HW / 128, THW / 128, B_);            // (8, 80, 4)
    gemm_p_kernel<<<g1, 256>>>(m_in, q_in, p);

    // 2) argmax -> gaussian centers
    argmax_kernel<<<(B_ * THW) / 8, 256>>>(p);

    // 3) fused gaussian-softmax: exp pass + reduce + scale
    dim3 g3(HW / 256, NCHUNK, B_);               // (4, 40, 4)
    exp_partial_kernel<<<g3, 256>>>(p, e);
    inv_kernel<<<(B_ * HW) / 256, 256>>>();
    scale_kernel<<<1184, 256>>>(e);

    // 4) memory readout GEMM -> out[:, :Do]
    dim3 g4(HW / 128, DO / 128, B_);             // (8, 4, 4)
    gemm_mem_kernel<<<g4, 256>>>(m_out, e, out);

    // 5) out[:, Do:] = q_out
    copy_qout_kernel<<<512, 256>>>(q_out, out);
}

// round 5
// speedup vs baseline: 1.7348x; 1.7348x over previous
#include <cuda_runtime.h>
#include <cuda_bf16.h>
#include <mma.h>
#include <cstdint>
#include <math.h>

using namespace nvcuda;

#define B_    4
#define DE    128
#define DO    512
#define THW   10240
#define HW    1024
#define NCHUNK 80
#define SCALE 0.08838834764831845f
#define INV2SIG2 (1.0f/18.0f)

// ---------------- device scratch ----------------
__device__ float         g_p[(size_t)B_ * THW * HW];       // p fp32, then e fp32 in-place
__device__ __nv_bfloat16 g_ehi[(size_t)B_ * HW * THW];     // e^T [b][q][t] hi
__device__ __nv_bfloat16 g_elo[(size_t)B_ * HW * THW];
__device__ __nv_bfloat16 g_mohi[(size_t)B_ * DO * THW];
__device__ __nv_bfloat16 g_molo[(size_t)B_ * DO * THW];
__device__ float         g_c[(size_t)B_ * DO * HW];        // raw GEMM2 result
__device__ float2        g_center[B_ * THW];
__device__ float         g_part[(size_t)B_ * NCHUNK * HW];
__device__ float         g_inv[B_ * HW];

// ============================================================
// fp32 SIMT GEMM1: p = mi^T qi / sqrt(De)   (argmax-exact)
// ============================================================
__global__ void __launch_bounds__(256) gemm_p_kernel(
    const float* __restrict__ mi, const float* __restrict__ qi, float* __restrict__ p)
{
    const int b = blockIdx.z;
    const float* A  = mi + (size_t)b * DE * THW;
    const float* Bq = qi + (size_t)b * DE * HW;
    float* C        = p  + (size_t)b * THW * HW;
    const int t0 = blockIdx.y * 128, q0 = blockIdx.x * 128;
    __shared__ float As[16][128], Bs[16][128];
    const int tid = threadIdx.x, tx = tid & 15, ty = tid >> 4;
    float acc[8][8];
    #pragma unroll
    for (int i = 0; i < 8; i++)
        #pragma unroll
        for (int j = 0; j < 8; j++) acc[i][j] = 0.f;
    for (int k0 = 0; k0 < DE; k0 += 16) {
        #pragma unroll
        for (int i = 0; i < 2; i++) {
            int idx = tid + i * 256, kk = idx >> 5, mm = (idx & 31) << 2;
            *(float4*)&As[kk][mm] = *(const float4*)(A + (size_t)(k0 + kk) * THW + t0 + mm);
            *(float4*)&Bs[kk][mm] = *(const float4*)(Bq + (size_t)(k0 + kk) * HW + q0 + mm);
        }
        __syncthreads();
        #pragma unroll
        for (int k = 0; k < 16; k++) {
            float ar[8], br[8];
            #pragma unroll
            for (int i = 0; i < 8; i++) ar[i] = As[k][ty * 8 + i];
            #pragma unroll
            for (int j = 0; j < 8; j++) br[j] = Bs[k][tx * 8 + j];
            #pragma unroll
            for (int i = 0; i < 8; i++)
                #pragma unroll
                for (int j = 0; j < 8; j++) acc[i][j] += ar[i] * br[j];
        }
        __syncthreads();
    }
    #pragma unroll
    for (int i = 0; i < 8; i++) {
        size_t row = (size_t)(t0 + ty * 8 + i) * HW + q0 + tx * 8;
        #pragma unroll
        for (int j = 0; j < 8; j += 4)
            *(float4*)(C + row + j) = make_float4(acc[i][j] * SCALE, acc[i][j+1] * SCALE,
                                                  acc[i][j+2] * SCALE, acc[i][j+3] * SCALE);
    }
}

// ============================================================
__global__ void __launch_bounds__(256) argmax_kernel(const float* __restrict__ p)
{
    int gw = (blockIdx.x * 256 + threadIdx.x) >> 5, lane = threadIdx.x & 31;
    if (gw >= B_ * THW) return;
    const float* row = p + (size_t)gw * HW;
    float best = -3.4e38f; int bi = 0;
    #pragma unroll 4
    for (int i = lane; i < HW; i += 32) { float v = row[i]; if (v > best) { best = v; bi = i; } }
    #pragma unroll
    for (int off = 16; off > 0; off >>= 1) {
        float ov = __shfl_down_sync(~0u, best, off);
        int   oi = __shfl_down_sync(~0u, bi, off);
        if (ov > best || (ov == best && oi < bi)) { best = ov; bi = oi; }
    }
    if (lane == 0) g_center[gw] = make_float2((float)(bi & 31), (float)(bi >> 5));
}

// ============================================================
// exp + transpose: e fp32 in-place over p, e^T bf16 hi/lo, partial sums.
// block handles 128 t x 32 q
// ============================================================
__global__ void __launch_bounds__(256) exp_t_kernel(float* __restrict__ p)
{
    __shared__ float tile[128][33];
    __shared__ float ssum[8][32];
    const int b = blockIdx.z, t0 = blockIdx.y * 128, q0 = blockIdx.x * 32;
    const int tid = threadIdx.x, tx = tid & 31, ty = tid >> 5;
    const float qx = (float)((q0 + tx) & 31), qy = (float)((q0 + tx) >> 5);
    float* pc = p + ((size_t)b * THW + t0) * HW + q0 + tx;
    const float2* cen = g_center + (size_t)b * THW + t0;
    float s = 0.f;
    #pragma unroll 4
    for (int r = 0; r < 16; r++) {
        int t = ty * 16 + r;
        float2 c = cen[t];
        float dx = qx - c.x, dy = qy - c.y;
        float v = __expf(pc[(size_t)t * HW] - (dx * dx + dy * dy) * INV2SIG2);
        pc[(size_t)t * HW] = v;       // e fp32 in place (for p_w output)
        tile[t][tx] = v;
        s += v;
    }
    ssum[ty][tx] = s;
    __syncthreads();
    if (ty == 0) {
        float a = 0.f;
        #pragma unroll
        for (int k = 0; k < 8; k++) a += ssum[k][tx];
        g_part[((size_t)b * NCHUNK + blockIdx.y) * HW + q0 + tx] = a;
    }
    // transposed bf16 hi/lo write: 32 q-rows, 128 t each
    const int qq = tid & 31, seg = tid >> 5;        // seg: 16 t's
    uint32_t hi[8], lo[8];
    #pragma unroll
    for (int k = 0; k < 8; k++) {
        float v0 = tile[seg * 16 + 2 * k][qq], v1 = tile[seg * 16 + 2 * k + 1][qq];
        __nv_bfloat16 h0 = __float2bfloat16(v0), h1 = __float2bfloat16(v1);
        hi[k] = ((uint32_t)*(uint16_t*)&h1 << 16) | *(uint16_t*)&h0;
        __nv_bfloat16 l0 = __float2bfloat16(v0 - __bfloat162float(h0));
        __nv_bfloat16 l1 = __float2bfloat16(v1 - __bfloat162float(h1));
        lo[k] = ((uint32_t)*(uint16_t*)&l1 << 16) | *(uint16_t*)&l0;
    }
    size_t o = ((size_t)b * HW + q0 + qq) * THW + t0 + seg * 16;
    *(uint4*)(g_ehi + o)     = make_uint4(hi[0], hi[1], hi[2], hi[3]);
    *(uint4*)(g_ehi + o + 8) = make_uint4(hi[4], hi[5], hi[6], hi[7]);
    *(uint4*)(g_elo + o)     = make_uint4(lo[0], lo[1], lo[2], lo[3]);
    *(uint4*)(g_elo + o + 8) = make_uint4(lo[4], lo[5], lo[6], lo[7]);
}

__global__ void __launch_bounds__(256) inv_kernel()
{
    int i = blockIdx.x * 256 + threadIdx.x;
    int b = i >> 10, q = i & 1023;
    float s = 0.f;
    #pragma unroll
    for (int c = 0; c < NCHUNK; c++) s += g_part[((size_t)b * NCHUNK + c) * HW + q];
    g_inv[i] = 1.0f / s;
}

// mo fp32 -> bf16 hi/lo
__global__ void __launch_bounds__(256) split_kernel(const float* __restrict__ in)
{
    const size_t n4 = (size_t)B_ * DO * THW / 4;
    const size_t stride = (size_t)gridDim.x * 256;
    for (size_t i = (size_t)blockIdx.x * 256 + threadIdx.x; i < n4; i += stride) {
        float4 v = ((const float4*)in)[i];
        __nv_bfloat16 h0 = __float2bfloat16(v.x), h1 = __float2bfloat16(v.y);
        __nv_bfloat16 h2 = __float2bfloat16(v.z), h3 = __float2bfloat16(v.w);
        __nv_bfloat162* H = (__nv_bfloat162*)g_mohi;
        __nv_bfloat162* L = (__nv_bfloat162*)g_molo;
        H[2*i]   = __halves2bfloat162(h0, h1);
        H[2*i+1] = __halves2bfloat162(h2, h3);
        L[2*i]   = __halves2bfloat162(__float2bfloat16(v.x - __bfloat162float(h0)),
                                      __float2bfloat16(v.y - __bfloat162float(h1)));
        L[2*i+1] = __halves2bfloat162(__float2bfloat16(v.z - __bfloat162float(h2)),
                                      __float2bfloat16(v.w - __bfloat162float(h3)));
    }
}

// ============================================================
// WMMA bf16 GEMM2: g_c = mo . e^T  (hi/lo, 3 passes)
// block tile 128(o) x 128(q), K chunk 32, 8 warps each 32x64
// A = mo [o][t] row-major (ld THW); B = e^T [q][t] (= col-major [t][q])
// ============================================================
#define KP 40   // padded k stride in smem (multiple of 8)

__global__ void __launch_bounds__(256) gemm2_wmma()
{
    __shared__ __nv_bfloat16 sAh[128][KP], sAl[128][KP];
    __shared__ __nv_bfloat16 sBh[128][KP], sBl[128][KP];

    const int b = blockIdx.z;
    const int q0 = blockIdx.x * 128, o0 = blockIdx.y * 128;
    const int tid = threadIdx.x, wid = tid >> 5;
    const int wm = wid & 3, wn = wid >> 2;     // 4 x 2 warp grid

    const __nv_bfloat16* Ah = g_mohi + ((size_t)b * DO + o0) * THW;
    const __nv_bfloat16* Al = g_molo + ((size_t)b * DO + o0) * THW;
    const __nv_bfloat16* Bh = g_ehi  + ((size_t)b * HW + q0) * THW;
    const __nv_bfloat16* Bl = g_elo  + ((size_t)b * HW + q0) * THW;

    wmma::fragment<wmma::accumulator, 16, 16, 16, float> fc[2][4];
    #pragma unroll
    for (int i = 0; i < 2; i++)
        #pragma unroll
        for (int j = 0; j < 4; j++) wmma::fill_fragment(fc[i][j], 0.f);

    for (int kc = 0; kc < THW; kc += 32) {
        // load 4 tiles of 128x32 bf16 (512 uint4 each)
        #pragma unroll
        for (int l = 0; l < 8; l++) {
            int idx = tid + l * 256;            // 0..2047
            int arr = idx >> 9;                 // 0..3
            int rem = idx & 511;
            int row = rem >> 2, j = (rem & 3) << 3;
            const __nv_bfloat16* src =
                (arr == 0 ? Ah : arr == 1 ? Al : arr == 2 ? Bh : Bl);
            uint4 v = *(const uint4*)(src + (size_t)row * THW + kc + j);
            __nv_bfloat16* dst =
                (arr == 0 ? &sAh[row][j] : arr == 1 ? &sAl[row][j] :
                 arr == 2 ? &sBh[row][j] : &sBl[row][j]);
            *(uint4*)dst = v;
        }
        __syncthreads();

        #pragma unroll
        for (int kk = 0; kk < 32; kk += 16) {
            wmma::fragment<wmma::matrix_a, 16, 16, 16, __nv_bfloat16, wmma::row_major> fah[2], fal[2];
            wmma::fragment<wmma::matrix_b, 16, 16, 16, __nv_bfloat16, wmma::col_major> fbh[4], fbl[4];
            #pragma unroll
            for (int i = 0; i < 2; i++) {
                wmma::load_matrix_sync(fah[i], &sAh[wm * 32 + i * 16][kk], KP);
                wmma::load_matrix_sync(fal[i], &sAl[wm * 32 + i * 16][kk], KP);
            }
            #pragma unroll
            for (int j = 0; j < 4; j++) {
                wmma::load_matrix_sync(fbh[j], &sBh[wn * 64 + j * 16][kk], KP);
                wmma::load_matrix_sync(fbl[j], &sBl[wn * 64 + j * 16][kk], KP);
            }
            #pragma unroll
            for (int i = 0; i < 2; i++)
                #pragma unroll
                for (int j = 0; j < 4; j++) {
                    wmma::mma_sync(fc[i][j], fah[i], fbh[j], fc[i][j]);
                    wmma::mma_sync(fc[i][j], fah[i], fbl[j], fc[i][j]);
                    wmma::mma_sync(fc[i][j], fal[i], fbh[j], fc[i][j]);
                }
        }
        __syncthreads();
    }

    float* C = g_c + ((size_t)b * DO + o0) * HW + q0;
    #pragma unroll
    for (int i = 0; i < 2; i++)
        #pragma unroll
        for (int j = 0; j < 4; j++)
            wmma::store_matrix_sync(C + (size_t)(wm * 32 + i * 16) * HW + wn * 64 + j * 16,
                                    fc[i][j], HW, wmma::mem_row_major);
}

// apply inv -> out[:, :Do]
__global__ void __launch_bounds__(256) combine_kernel(float* __restrict__ out)
{
    const size_t n4 = (size_t)B_ * DO * HW / 4;
    size_t i = (size_t)blockIdx.x * 256 + threadIdx.x;
    if (i >= n4) return;
    float4 a = ((const float4*)g_c)[i];
    size_t q4 = i & 255;
    size_t b  = i / ((size_t)DO * HW / 4);
    float4 inv = ((const float4*)g_inv)[b * 256 + q4];
    float4 v = make_float4(a.x * inv.x, a.y * inv.y, a.z * inv.z, a.w * inv.w);
    size_t r = i - b * ((size_t)DO * HW / 4);
    ((float4*)out)[b * ((size_t)2 * DO * HW / 4) + r] = v;
}

__global__ void __launch_bounds__(256) copy_qout_kernel(
    const float* __restrict__ q_out, float* __restrict__ out)
{
    const size_t per_b4 = (size_t)DO * HW / 4;
    size_t i = (size_t)blockIdx.x * 256 + threadIdx.x;
    if (i >= (size_t)B_ * per_b4) return;
    size_t b = i / per_b4, r = i - b * per_b4;
    ((float4*)out)[b * 2 * per_b4 + per_b4 + r] = ((const float4*)q_out)[i];
}

// p_w fp32 (optional second output): out_tail = e * inv
__global__ void __launch_bounds__(256) pw_kernel(float* __restrict__ dst)
{
    const size_t total4 = (size_t)B_ * THW * HW / 4;
    const size_t stride = (size_t)gridDim.x * 256;
    for (size_t i = (size_t)blockIdx.x * 256 + threadIdx.x; i < total4; i += stride) {
        float4 v = ((const float4*)g_p)[i];
        size_t q4 = i & 255;
        size_t b  = i / ((size_t)THW * HW / 4);
        float4 inv = ((const float4*)g_inv)[b * 256 + q4];
        ((float4*)dst)[i] = make_float4(v.x * inv.x, v.y * inv.y, v.z * inv.z, v.w * inv.w);
    }
}

// ============================================================
extern "C" void kernel_launch(void* const* d_in, const int* in_sizes, int n_in,
                              void* d_out, int out_size)
{
    const float* m_in  = (const float*)d_in[0];
    const float* m_out = (const float*)d_in[1];
    const float* q_in  = (const float*)d_in[2];
    const float* q_out = (const float*)d_in[3];
    float* out = (float*)d_out;

    float* p = nullptr;
    cudaGetSymbolAddress((void**)&p, g_p);

    // 1) p = mi^T qi / sqrt(De)  (fp32, argmax-exact)
    dim3 g1(HW / 128, THW / 128, B_);
    gemm_p_kernel<<<g1, 256>>>(m_in, q_in, p);

    // 2) split mo -> bf16 hi/lo
    split_kernel<<<4096, 256>>>(m_out);

    // 3) argmax -> centers
    argmax_kernel<<<(B_ * THW) / 8, 256>>>(p);

    // 4) exp + transpose + partial sums
    dim3 g3(HW / 32, THW / 128, B_);
    exp_t_kernel<<<g3, 256>>>(p);

    // 5) inv
    inv_kernel<<<(B_ * HW) / 256, 256>>>();

    // 6) WMMA bf16 GEMM2
    dim3 g4(HW / 128, DO / 128, B_);    // (8, 4, 4) = 128 CTAs
    gemm2_wmma<<<g4, 256>>>();

    // 7) normalize -> out[:, :Do]
    combine_kernel<<<(B_ * DO * HW / 4 + 255) / 256, 256>>>(out);

    // 8) out[:, Do:] = q_out
    copy_qout_kernel<<<(B_ * DO * HW / 4 + 255) / 256, 256>>>(q_out, out);

    // 9) optional p_w output
    const size_t memout = (size_t)B_ * 2 * DO * HW;
    const size_t pw     = (size_t)B_ * THW * HW;
    if ((size_t)out_size >= memout + pw)
        pw_kernel<<<2368, 256>>>(out + memout);
}

// round 6
// speedup vs baseline: 1.9940x; 1.1494x over previous
#include <cuda_runtime.h>
#include <cuda_bf16.h>
#include <mma.h>
#include <cstdint>
#include <math.h>

using namespace nvcuda;

#define B_    4
#define DE    128
#define DO    512
#define THW   10240
#define HW    1024
#define NCHUNK 80
#define SCALE 0.08838834764831845f
#define INV2SIG2 (1.0f/18.0f)

// ---------------- device scratch ----------------
__device__ float         g_p[(size_t)B_ * THW * HW];       // p fp32 (preserved)
__device__ __nv_bfloat16 g_ehi[(size_t)B_ * HW * THW];     // e^T [b][q][t] hi
__device__ __nv_bfloat16 g_elo[(size_t)B_ * HW * THW];
__device__ __nv_bfloat16 g_mohi[(size_t)B_ * DO * THW];
__device__ __nv_bfloat16 g_molo[(size_t)B_ * DO * THW];
__device__ float         g_c[(size_t)B_ * DO * HW];        // raw GEMM2 result
__device__ float2        g_center[B_ * THW];
__device__ float2        g_amax[(size_t)B_ * THW * 8];     // per-qtile argmax partials
__device__ float         g_part[(size_t)B_ * NCHUNK * HW];
__device__ float         g_inv[B_ * HW];

// ============================================================
// fp32 SIMT GEMM1: p = mi^T qi / sqrt(De)  + fused per-tile argmax partials
// ============================================================
__global__ void __launch_bounds__(256) gemm_p_kernel(
    const float* __restrict__ mi, const float* __restrict__ qi, float* __restrict__ p)
{
    const int b = blockIdx.z;
    const float* A  = mi + (size_t)b * DE * THW;
    const float* Bq = qi + (size_t)b * DE * HW;
    float* C        = p  + (size_t)b * THW * HW;
    const int t0 = blockIdx.y * 128, q0 = blockIdx.x * 128;
    __shared__ float As[16][128], Bs[16][128];
    const int tid = threadIdx.x, tx = tid & 15, ty = tid >> 4;
    float acc[8][8];
    #pragma unroll
    for (int i = 0; i < 8; i++)
        #pragma unroll
        for (int j = 0; j < 8; j++) acc[i][j] = 0.f;
    for (int k0 = 0; k0 < DE; k0 += 16) {
        #pragma unroll
        for (int i = 0; i < 2; i++) {
            int idx = tid + i * 256, kk = idx >> 5, mm = (idx & 31) << 2;
            *(float4*)&As[kk][mm] = *(const float4*)(A + (size_t)(k0 + kk) * THW + t0 + mm);
            *(float4*)&Bs[kk][mm] = *(const float4*)(Bq + (size_t)(k0 + kk) * HW + q0 + mm);
        }
        __syncthreads();
        #pragma unroll
        for (int k = 0; k < 16; k++) {
            float ar[8], br[8];
            #pragma unroll
            for (int i = 0; i < 8; i++) ar[i] = As[k][ty * 8 + i];
            #pragma unroll
            for (int j = 0; j < 8; j++) br[j] = Bs[k][tx * 8 + j];
            #pragma unroll
            for (int i = 0; i < 8; i++)
                #pragma unroll
                for (int j = 0; j < 8; j++) acc[i][j] += ar[i] * br[j];
        }
        __syncthreads();
    }
    #pragma unroll
    for (int i = 0; i < 8; i++) {
        size_t row = (size_t)(t0 + ty * 8 + i) * HW + q0 + tx * 8;
        #pragma unroll
        for (int j = 0; j < 8; j += 4)
            *(float4*)(C + row + j) = make_float4(acc[i][j] * SCALE, acc[i][j+1] * SCALE,
                                                  acc[i][j+2] * SCALE, acc[i][j+3] * SCALE);
    }
    // fused per-row argmax partial over this 128-wide q tile
    #pragma unroll
    for (int i = 0; i < 8; i++) {
        float bv = acc[i][0];
        int bj = 0;
        #pragma unroll
        for (int j = 1; j < 8; j++)
            if (acc[i][j] > bv) { bv = acc[i][j]; bj = j; }
        int gq = q0 + tx * 8 + bj;
        #pragma unroll
        for (int off = 8; off > 0; off >>= 1) {
            float ov = __shfl_down_sync(~0u, bv, off, 16);
            int   oi = __shfl_down_sync(~0u, gq, off, 16);
            if (ov > bv || (ov == bv && oi < gq)) { bv = ov; gq = oi; }
        }
        if (tx == 0)
            g_amax[((size_t)b * THW + t0 + ty * 8 + i) * 8 + blockIdx.x] =
                make_float2(bv, (float)gq);
    }
}

// reduce 8 tile-partials per row -> gaussian center
__global__ void __launch_bounds__(256) argmax_final()
{
    int r = blockIdx.x * 256 + threadIdx.x;
    if (r >= B_ * THW) return;
    const float2* a = g_amax + (size_t)r * 8;
    float bv = a[0].x;
    int bi = (int)a[0].y;
    #pragma unroll
    for (int k = 1; k < 8; k++) {
        float2 v = a[k];
        if (v.x > bv) { bv = v.x; bi = (int)v.y; }   // ascending q-tiles: keeps first max
    }
    g_center[r] = make_float2((float)(bi & 31), (float)(bi >> 5));
}

// ============================================================
// exp + transpose: e^T bf16 hi/lo + partial sums (p preserved)
// block handles 128 t x 32 q
// ============================================================
__global__ void __launch_bounds__(256) exp_t_kernel(const float* __restrict__ p)
{
    __shared__ float tile[128][33];
    __shared__ float ssum[8][32];
    const int b = blockIdx.z, t0 = blockIdx.y * 128, q0 = blockIdx.x * 32;
    const int tid = threadIdx.x, tx = tid & 31, ty = tid >> 5;
    const float qx = (float)((q0 + tx) & 31), qy = (float)((q0 + tx) >> 5);
    const float* pc = p + ((size_t)b * THW + t0) * HW + q0 + tx;
    const float2* cen = g_center + (size_t)b * THW + t0;
    float s = 0.f;
    #pragma unroll 4
    for (int r = 0; r < 16; r++) {
        int t = ty * 16 + r;
        float2 c = cen[t];
        float dx = qx - c.x, dy = qy - c.y;
        float v = __expf(pc[(size_t)t * HW] - (dx * dx + dy * dy) * INV2SIG2);
        tile[t][tx] = v;
        s += v;
    }
    ssum[ty][tx] = s;
    __syncthreads();
    if (ty == 0) {
        float a = 0.f;
        #pragma unroll
        for (int k = 0; k < 8; k++) a += ssum[k][tx];
        g_part[((size_t)b * NCHUNK + blockIdx.y) * HW + q0 + tx] = a;
    }
    const int qq = tid & 31, seg = tid >> 5;
    uint32_t hi[8], lo[8];
    #pragma unroll
    for (int k = 0; k < 8; k++) {
        float v0 = tile[seg * 16 + 2 * k][qq], v1 = tile[seg * 16 + 2 * k + 1][qq];
        __nv_bfloat16 h0 = __float2bfloat16(v0), h1 = __float2bfloat16(v1);
        hi[k] = ((uint32_t)*(uint16_t*)&h1 << 16) | *(uint16_t*)&h0;
        __nv_bfloat16 l0 = __float2bfloat16(v0 - __bfloat162float(h0));
        __nv_bfloat16 l1 = __float2bfloat16(v1 - __bfloat162float(h1));
        lo[k] = ((uint32_t)*(uint16_t*)&l1 << 16) | *(uint16_t*)&l0;
    }
    size_t o = ((size_t)b * HW + q0 + qq) * THW + t0 + seg * 16;
    *(uint4*)(g_ehi + o)     = make_uint4(hi[0], hi[1], hi[2], hi[3]);
    *(uint4*)(g_ehi + o + 8) = make_uint4(hi[4], hi[5], hi[6], hi[7]);
    *(uint4*)(g_elo + o)     = make_uint4(lo[0], lo[1], lo[2], lo[3]);
    *(uint4*)(g_elo + o + 8) = make_uint4(lo[4], lo[5], lo[6], lo[7]);
}

__global__ void __launch_bounds__(256) inv_kernel()
{
    int i = blockIdx.x * 256 + threadIdx.x;
    int b = i >> 10, q = i & 1023;
    float s = 0.f;
    #pragma unroll
    for (int c = 0; c < NCHUNK; c++) s += g_part[((size_t)b * NCHUNK + c) * HW + q];
    g_inv[i] = 1.0f / s;
}

// mo fp32 -> bf16 hi/lo
__global__ void __launch_bounds__(256) split_kernel(const float* __restrict__ in)
{
    const size_t n4 = (size_t)B_ * DO * THW / 4;
    const size_t stride = (size_t)gridDim.x * 256;
    for (size_t i = (size_t)blockIdx.x * 256 + threadIdx.x; i < n4; i += stride) {
        float4 v = ((const float4*)in)[i];
        __nv_bfloat16 h0 = __float2bfloat16(v.x), h1 = __float2bfloat16(v.y);
        __nv_bfloat16 h2 = __float2bfloat16(v.z), h3 = __float2bfloat16(v.w);
        __nv_bfloat162* H = (__nv_bfloat162*)g_mohi;
        __nv_bfloat162* L = (__nv_bfloat162*)g_molo;
        H[2*i]   = __halves2bfloat162(h0, h1);
        H[2*i+1] = __halves2bfloat162(h2, h3);
        L[2*i]   = __halves2bfloat162(__float2bfloat16(v.x - __bfloat162float(h0)),
                                      __float2bfloat16(v.y - __bfloat162float(h1)));
        L[2*i+1] = __halves2bfloat162(__float2bfloat16(v.z - __bfloat162float(h2)),
                                      __float2bfloat16(v.w - __bfloat162float(h3)));
    }
}

// ============================================================
// WMMA bf16 GEMM2 with cp.async 3-stage pipeline:
// g_c = mo . e^T (hi/lo, 3 passes), tile 128(o)x128(q), K-chunk 32
// ============================================================
#define KP 40
#define NSTAGE 3
#define TILE_ELEMS (128 * KP)                    // bf16 elems per tile
#define STAGE_ELEMS (4 * TILE_ELEMS)
#define SMEM_DYN (NSTAGE * STAGE_ELEMS * 2)      // 122880 bytes

__device__ __forceinline__ void cp16(uint32_t sa, const void* g) {
    asm volatile("cp.async.cg.shared.global [%0], [%1], 16;" :: "r"(sa), "l"(g));
}

__global__ void __launch_bounds__(256) gemm2_wmma()
{
    extern __shared__ __nv_bfloat16 dsm[];
    const int b = blockIdx.z;
    const int q0 = blockIdx.x * 128, o0 = blockIdx.y * 128;
    const int tid = threadIdx.x, wid = tid >> 5;
    const int wm = wid & 3, wn = wid >> 2;       // 4 x 2 warp grid, warp tile 32x64

    const __nv_bfloat16* Ah = g_mohi + ((size_t)b * DO + o0) * THW;
    const __nv_bfloat16* Al = g_molo + ((size_t)b * DO + o0) * THW;
    const __nv_bfloat16* Bh = g_ehi  + ((size_t)b * HW + q0) * THW;
    const __nv_bfloat16* Bl = g_elo  + ((size_t)b * HW + q0) * THW;

    const uint32_t sbase = (uint32_t)__cvta_generic_to_shared(dsm);

    // stage loader: 4 tiles x 128 rows x 64B, 8 cp.async per thread
    auto load_stage = [&](int slot, int kc) {
        uint32_t sb = sbase + (uint32_t)slot * (STAGE_ELEMS * 2);
        #pragma unroll
        for (int l = 0; l < 8; l++) {
            int idx = tid + l * 256;
            int arr = idx >> 9, rem = idx & 511;
            int row = rem >> 2, ch = rem & 3;
            const __nv_bfloat16* src =
                (arr == 0 ? Ah : arr == 1 ? Al : arr == 2 ? Bh : Bl);
            uint32_t sa = sb + (uint32_t)arr * (TILE_ELEMS * 2) + row * (KP * 2) + ch * 16;
            cp16(sa, src + (size_t)row * THW + kc + ch * 8);
        }
    };

    wmma::fragment<wmma::accumulator, 16, 16, 16, float> fc[2][4];
    #pragma unroll
    for (int i = 0; i < 2; i++)
        #pragma unroll
        for (int j = 0; j < 4; j++) wmma::fill_fragment(fc[i][j], 0.f);

    const int NC = THW / 32;   // 320

    #pragma unroll
    for (int s = 0; s < NSTAGE - 1; s++) {
        load_stage(s, s * 32);
        asm volatile("cp.async.commit_group;" ::: "memory");
    }

    for (int c = 0; c < NC; c++) {
        asm volatile("cp.async.wait_group %0;" :: "n"(NSTAGE - 2) : "memory");
        __syncthreads();
        int nl = c + NSTAGE - 1;
        if (nl < NC) load_stage(nl % NSTAGE, nl * 32);
        asm volatile("cp.async.commit_group;" ::: "memory");

        __nv_bfloat16* st  = dsm + (size_t)(c % NSTAGE) * STAGE_ELEMS;
        __nv_bfloat16* tAh = st;
        __nv_bfloat16* tAl = st + TILE_ELEMS;
        __nv_bfloat16* tBh = st + 2 * TILE_ELEMS;
        __nv_bfloat16* tBl = st + 3 * TILE_ELEMS;

        #pragma unroll
        for (int kk = 0; kk < 32; kk += 16) {
            wmma::fragment<wmma::matrix_a, 16, 16, 16, __nv_bfloat16, wmma::row_major> fah[2], fal[2];
            wmma::fragment<wmma::matrix_b, 16, 16, 16, __nv_bfloat16, wmma::col_major> fbh[4], fbl[4];
            #pragma unroll
            for (int i = 0; i < 2; i++) {
                wmma::load_matrix_sync(fah[i], tAh + (wm * 32 + i * 16) * KP + kk, KP);
                wmma::load_matrix_sync(fal[i], tAl + (wm * 32 + i * 16) * KP + kk, KP);
            }
            #pragma unroll
            for (int j = 0; j < 4; j++) {
                wmma::load_matrix_sync(fbh[j], tBh + (wn * 64 + j * 16) * KP + kk, KP);
                wmma::load_matrix_sync(fbl[j], tBl + (wn * 64 + j * 16) * KP + kk, KP);
            }
            #pragma unroll
            for (int i = 0; i < 2; i++)
                #pragma unroll
                for (int j = 0; j < 4; j++) {
                    wmma::mma_sync(fc[i][j], fah[i], fbh[j], fc[i][j]);
                    wmma::mma_sync(fc[i][j], fah[i], fbl[j], fc[i][j]);
                    wmma::mma_sync(fc[i][j], fal[i], fbh[j], fc[i][j]);
                }
        }
    }
    asm volatile("cp.async.wait_group 0;" ::: "memory");

    float* C = g_c + ((size_t)b * DO + o0) * HW + q0;
    #pragma unroll
    for (int i = 0; i < 2; i++)
        #pragma unroll
        for (int j = 0; j < 4; j++)
            wmma::store_matrix_sync(C + (size_t)(wm * 32 + i * 16) * HW + wn * 64 + j * 16,
                                    fc[i][j], HW, wmma::mem_row_major);
}

// apply inv -> out[:, :Do]
__global__ void __launch_bounds__(256) combine_kernel(float* __restrict__ out)
{
    const size_t n4 = (size_t)B_ * DO * HW / 4;
    size_t i = (size_t)blockIdx.x * 256 + threadIdx.x;
    if (i >= n4) return;
    float4 a = ((const float4*)g_c)[i];
    size_t q4 = i & 255;
    size_t b  = i / ((size_t)DO * HW / 4);
    float4 inv = ((const float4*)g_inv)[b * 256 + q4];
    float4 v = make_float4(a.x * inv.x, a.y * inv.y, a.z * inv.z, a.w * inv.w);
    size_t r = i - b * ((size_t)DO * HW / 4);
    ((float4*)out)[b * ((size_t)2 * DO * HW / 4) + r] = v;
}

__global__ void __launch_bounds__(256) copy_qout_kernel(
    const float* __restrict__ q_out, float* __restrict__ out)
{
    const size_t per_b4 = (size_t)DO * HW / 4;
    size_t i = (size_t)blockIdx.x * 256 + threadIdx.x;
    if (i >= (size_t)B_ * per_b4) return;
    size_t b = i / per_b4, r = i - b * per_b4;
    ((float4*)out)[b * 2 * per_b4 + per_b4 + r] = ((const float4*)q_out)[i];
}

// p_w fp32 output: recompute exp from preserved p, apply inv
__global__ void __launch_bounds__(256) pw_kernel(const float* __restrict__ p,
                                                 float* __restrict__ dst)
{
    const size_t total4 = (size_t)B_ * THW * HW / 4;
    const size_t stride = (size_t)gridDim.x * 256;
    for (size_t i = (size_t)blockIdx.x * 256 + threadIdx.x; i < total4; i += stride) {
        float4 v = ((const float4*)p)[i];
        size_t bt = i >> 8;                  // b*THW + t
        int q4 = (int)(i & 255);
        int qbase = q4 * 4;
        size_t b = bt / THW;
        float2 c = g_center[bt];
        float4 inv = ((const float4*)g_inv)[b * 256 + q4];
        float qy = (float)(qbase >> 5);
        float dy2 = (qy - c.y) * (qy - c.y);
        float4 r;
        {
            float dx = (float)((qbase + 0) & 31) - c.x;
            r.x = __expf(v.x - (dx * dx + dy2) * INV2SIG2) * inv.x;
        }
        {
            float dx = (float)((qbase + 1) & 31) - c.x;
            r.y = __expf(v.y - (dx * dx + dy2) * INV2SIG2) * inv.y;
        }
        {
            float dx = (float)((qbase + 2) & 31) - c.x;
            r.z = __expf(v.z - (dx * dx + dy2) * INV2SIG2) * inv.z;
        }
        {
            float dx = (float)((qbase + 3) & 31) - c.x;
            r.w = __expf(v.w - (dx * dx + dy2) * INV2SIG2) * inv.w;
        }
        ((float4*)dst)[i] = r;
    }
}

// ============================================================
extern "C" void kernel_launch(void* const* d_in, const int* in_sizes, int n_in,
                              void* d_out, int out_size)
{
    const float* m_in  = (const float*)d_in[0];
    const float* m_out = (const float*)d_in[1];
    const float* q_in  = (const float*)d_in[2];
    const float* q_out = (const float*)d_in[3];
    float* out = (float*)d_out;

    float* p = nullptr;
    cudaGetSymbolAddress((void**)&p, g_p);

    cudaFuncSetAttribute(gemm2_wmma, cudaFuncAttributeMaxDynamicSharedMemorySize, SMEM_DYN);

    // 1) p = mi^T qi / sqrt(De)  (fp32, argmax-exact) + argmax partials
    dim3 g1(HW / 128, THW / 128, B_);
    gemm_p_kernel<<<g1, 256>>>(m_in, q_in, p);

    // 2) split mo -> bf16 hi/lo
    split_kernel<<<4096, 256>>>(m_out);

    // 3) argmax final reduce -> centers
    argmax_final<<<(B_ * THW + 255) / 256, 256>>>();

    // 4) exp + transpose + partial sums (p preserved)
    dim3 g3(HW / 32, THW / 128, B_);
    exp_t_kernel<<<g3, 256>>>(p);

    // 5) inv
    inv_kernel<<<(B_ * HW) / 256, 256>>>();

    // 6) WMMA bf16 GEMM2, cp.async pipelined
    dim3 g4(HW / 128, DO / 128, B_);    // 128 CTAs
    gemm2_wmma<<<g4, 256, SMEM_DYN>>>();

    // 7) normalize -> out[:, :Do]
    combine_kernel<<<(B_ * DO * HW / 4 + 255) / 256, 256>>>(out);

    // 8) out[:, Do:] = q_out
    copy_qout_kernel<<<(B_ * DO * HW / 4 + 255) / 256, 256>>>(q_out, out);

    // 9) optional p_w output (recomputed from preserved p)
    const size_t memout = (size_t)B_ * 2 * DO * HW;
    const size_t pw     = (size_t)B_ * THW * HW;
    if ((size_t)out_size >= memout + pw)
        pw_kernel<<<4096, 256>>>(p, out + memout);
}